// round 9
// baseline (speedup 1.0000x reference)
#include <cuda_runtime.h>
#include <math.h>

#define IMGSZ 224
#define HW (IMGSZ*IMGSZ)     // 50176
#define NK 100
#define NP 16
#define NB 8
#define NT 196               // 14x14 tiles of 16x16 px
#define NITER 10

#define FIXSCALE 68719476736.0f   // 2^36
typedef unsigned long long u64;

// ---------------- device scratch (static, no runtime alloc) ----------------
__device__ float g_A[NP*IMGSZ];                   // resize matrix [16,224]
__device__ float g_centers[NB][NK][5];            // SLIC centers (persisted for empty-cluster fallback)
__device__ unsigned char g_labels[NB][HW];        // per-pixel labels
__device__ u64 g_sum[NITER][NB][NK][6];           // per-iteration exact int64 sums (384 KB)
__device__ float g_acc[NB][NK][NP][NP][3];        // output accumulator (2.4 MB)

__device__ __forceinline__ float slic_ratio() {
    return (float)(10.0 / sqrt(224.0 * 224.0 / 100.0));
}

// ---------------- init: A, centers, zero g_sum + g_acc ----------------
__global__ void k_init(const float* __restrict__ x) {
    int b = blockIdx.x;
    int part = blockIdx.y;           // 0..3
    int t = threadIdx.x;

    if (part == 0) {
        if (b == 0 && t < NP) {
            float sample = (t + 0.5f) * 14.0f - 0.5f;
            float total = 0.0f;
            for (int h = 0; h < IMGSZ; h++) {
                float d = fabsf(sample - (float)h) * (1.0f / 14.0f);
                float w = fmaxf(0.0f, 1.0f - d);
                g_A[t * IMGSZ + h] = w;
                total += w;
            }
            float inv = 1.0f / total;
            for (int h = 0; h < IMGSZ; h++) g_A[t * IMGSZ + h] *= inv;
        }
        if (t < NK) {
            const int cg[10] = {11, 33, 56, 78, 100, 123, 145, 168, 190, 212};
            int gy = t / 10, gx = t % 10;
            int h = cg[gy], w = cg[gx];
            const float* im = x + (size_t)b * 3 * HW;
            float ratio = slic_ratio();
            g_centers[b][t][0] = im[0 * HW + h * IMGSZ + w];
            g_centers[b][t][1] = im[1 * HW + h * IMGSZ + w];
            g_centers[b][t][2] = im[2 * HW + h * IMGSZ + w];
            g_centers[b][t][3] = (float)h * ratio;
            g_centers[b][t][4] = (float)w * ratio;
        }
    }
    // zero g_sum slice for image b (NITER*NK*6 = 6000 u64), split over 4 parts
    {
        u64* gs = &g_sum[0][b][0][0];   // stride between iters = NB*NK*6
        for (int j = part * 256 + t; j < NITER * NK * 6; j += 1024) {
            int it = j / (NK * 6), r = j % (NK * 6);
            g_sum[it][b][0][r] = 0ull;
            (void)gs;
        }
    }
    // zero g_acc slice for image b (76800 floats), split over 4 parts
    {
        float4* ga = reinterpret_cast<float4*>(&g_acc[b][0][0][0][0]);
        for (int j = part * 256 + t; j < NK * NP * NP * 3 / 4; j += 1024)
            ga[j] = make_float4(0.f, 0.f, 0.f, 0.f);
    }
}

// ---------------- fused (center recompute) + assign + int64 sums ------------
// One block per 16x16 tile. Prologue: for iter>0, recompute centers from the
// previous iteration's exact int64 sums (Newton-refined reciprocal, ~2^-44
// rel err); persist to g_centers when cnt>0 (all blocks write identical
// values; cnt==0 readers see last valid center => matches jnp.where).
// Candidate pruning: center k excluded iff rectMinSpatial2(k) >
// min_j rectMaxSpatial2(j) + 3 (colors in [0,1)). Conservative => labels
// identical to full argmin. Accumulation: features scaled by 2^36 as u64,
// warp-segmented exact butterfly + one leader atomic per (warp,label).
__global__ __launch_bounds__(256) void k_assign_tile(const float* __restrict__ x,
                                                     int iter, int accumulate) {
    __shared__ float scen[NK][5];
    __shared__ float scen2[NK];
    __shared__ unsigned char scand[NK];
    __shared__ unsigned int bal[8];
    __shared__ int sminbits;

    int tile = blockIdx.x, b = blockIdx.y, t = threadIdx.x;
    int lane = t & 31, warp = t >> 5;
    const float ratio = slic_ratio();
    int tr = tile / 14, tc = tile - tr * 14;

    if (t == 0) sminbits = 0x7f7fffff;   // +FLT_MAX
    __syncthreads();

    // ---- center recompute (fused reduce) + candidate prologue ----
    float rmin = 1e30f, rmax = 1e30f;
    float c0 = 0.f, c1 = 0.f, c2 = 0.f, c3 = 0.f, c4 = 0.f;
    if (t < NK) {
        if (iter == 0) {
            c0 = g_centers[b][t][0];
            c1 = g_centers[b][t][1];
            c2 = g_centers[b][t][2];
            c3 = g_centers[b][t][3];
            c4 = g_centers[b][t][4];
        } else {
            const u64* gs = &g_sum[iter - 1][b][t][0];
            u64 a0 = gs[0], a1 = gs[1], a2 = gs[2], a3 = gs[3], a4 = gs[4], a5 = gs[5];
            if (a5 > 0ull) {
                double denom = (double)a5 * 68719476736.0;
                double r = (double)__frcp_rn((float)denom);
                r = r * (2.0 - denom * r);          // Newton: rel err ~2^-44
                c0 = (float)((double)a0 * r);
                c1 = (float)((double)a1 * r);
                c2 = (float)((double)a2 * r);
                c3 = (float)((double)a3 * r);
                c4 = (float)((double)a4 * r);
                g_centers[b][t][0] = c0;            // persist (identical values => race-free)
                g_centers[b][t][1] = c1;
                g_centers[b][t][2] = c2;
                g_centers[b][t][3] = c3;
                g_centers[b][t][4] = c4;
            } else {
                c0 = g_centers[b][t][0];
                c1 = g_centers[b][t][1];
                c2 = g_centers[b][t][2];
                c3 = g_centers[b][t][3];
                c4 = g_centers[b][t][4];
            }
        }
        float ylo = (float)(tr * 16) * ratio, yhi = (float)(tr * 16 + 15) * ratio;
        float xlo = (float)(tc * 16) * ratio, xhi = (float)(tc * 16 + 15) * ratio;
        float dy0 = fmaxf(0.0f, fmaxf(ylo - c3, c3 - yhi));
        float dx0 = fmaxf(0.0f, fmaxf(xlo - c4, c4 - xhi));
        float dy1 = fmaxf(c3 - ylo, yhi - c3);
        float dx1 = fmaxf(c4 - xlo, xhi - c4);
        rmin = dy0 * dy0 + dx0 * dx0;
        rmax = dy1 * dy1 + dx1 * dx1;
    }
    float v = rmax;
#pragma unroll
    for (int o = 16; o; o >>= 1) v = fminf(v, __shfl_xor_sync(0xffffffffu, v, o));
    if (lane == 0) atomicMin(&sminbits, __float_as_int(v));
    __syncthreads();
    float thresh = __int_as_float(sminbits) + 3.001f;
    bool keep = (t < NK) && (rmin <= thresh);
    unsigned int m = __ballot_sync(0xffffffffu, keep);
    if (lane == 0) bal[warp] = m;
    __syncthreads();
    if (keep) {
        int slot = __popc(m & ((1u << lane) - 1u));
        for (int w = 0; w < warp; w++) slot += __popc(bal[w]);
        scand[slot] = (unsigned char)t;
        scen[slot][0] = c0; scen[slot][1] = c1; scen[slot][2] = c2;
        scen[slot][3] = c3; scen[slot][4] = c4;
        scen2[slot] = c0*c0 + c1*c1 + c2*c2 + c3*c3 + c4*c4;
    }
    __syncthreads();
    int nc = 0;
#pragma unroll
    for (int w = 0; w < 8; w++) nc += __popc(bal[w]);

    // ---- per-pixel assignment ----
    int py = tr * 16 + (t >> 4), px = tc * 16 + (t & 15);
    int i = py * IMGSZ + px;
    const float* im = x + (size_t)b * 3 * HW;
    float f0 = im[i];
    float f1 = im[HW + i];
    float f2 = im[2 * HW + i];
    float f3 = (float)py * ratio;
    float f4 = (float)px * ratio;
    float fsq = f0*f0 + f1*f1 + f2*f2 + f3*f3 + f4*f4;

    float best = 3.4e38f;
    int bs = 0;
    for (int s = 0; s < nc; s++) {
        float dot = f0 * scen[s][0];
        dot = fmaf(f1, scen[s][1], dot);
        dot = fmaf(f2, scen[s][2], dot);
        dot = fmaf(f3, scen[s][3], dot);
        dot = fmaf(f4, scen[s][4], dot);
        float d = fsq + scen2[s] - 2.0f * dot;
        if (d < best) { best = d; bs = s; }   // strict < + ascending k => first-min
    }
    int kk = scand[bs];
    g_labels[b][i] = (unsigned char)kk;

    if (!accumulate) return;

    // ---- warp-segmented exact int64 accumulation ----
    u64 q0 = (u64)__float2ll_rn(f0 * FIXSCALE);
    u64 q1 = (u64)__float2ll_rn(f1 * FIXSCALE);
    u64 q2 = (u64)__float2ll_rn(f2 * FIXSCALE);
    u64 q3 = (u64)__float2ll_rn(f3 * FIXSCALE);
    u64 q4 = (u64)__float2ll_rn(f4 * FIXSCALE);

    unsigned int rem = 0xffffffffu;
    while (rem) {
        int leader = __ffs((int)rem) - 1;
        int lk = __shfl_sync(0xffffffffu, kk, leader);
        bool mine = (kk == lk);
        unsigned int mm = __ballot_sync(0xffffffffu, mine);
        u64 v0 = mine ? q0 : 0ull;
        u64 v1 = mine ? q1 : 0ull;
        u64 v2 = mine ? q2 : 0ull;
        u64 v3 = mine ? q3 : 0ull;
        u64 v4 = mine ? q4 : 0ull;
#pragma unroll
        for (int o = 16; o; o >>= 1) {
            v0 += __shfl_xor_sync(0xffffffffu, v0, o);
            v1 += __shfl_xor_sync(0xffffffffu, v1, o);
            v2 += __shfl_xor_sync(0xffffffffu, v2, o);
            v3 += __shfl_xor_sync(0xffffffffu, v3, o);
            v4 += __shfl_xor_sync(0xffffffffu, v4, o);
        }
        if (lane == leader) {
            u64* gs = &g_sum[iter][b][lk][0];
            atomicAdd(gs + 0, v0);
            atomicAdd(gs + 1, v1);
            atomicAdd(gs + 2, v2);
            atomicAdd(gs + 3, v3);
            atomicAdd(gs + 4, v4);
            atomicAdd(gs + 5, (u64)__popc(mm));
        }
        rem &= ~mm;
    }
}

// ---------------- scatter: pixel -> g_acc[b][k][p][q][c] (warp-aggregated) --
// warp = 32-pixel row segment; p-support & weights are warp-uniform (same h).
// For each distinct label in the warp and each q in the segment's support:
// 3-channel butterfly of wtq*rgb over member lanes, leader REDGs wtp*sum.
__global__ __launch_bounds__(256) void k_scatter(const float* __restrict__ x) {
    int b = blockIdx.y;
    int wi = blockIdx.x * 8 + (threadIdx.x >> 5);    // 0..1567
    int lane = threadIdx.x & 31;
    int h = wi / 7, seg = wi - (wi / 7) * 7;
    int w = seg * 32 + lane;
    int i = h * IMGSZ + w;
    const float* im = x + (size_t)b * 3 * HW;
    float r = im[i], g = im[HW + i], bl = im[2 * HW + i];
    int kk = g_labels[b][i];

    int p0 = max(0, (int)ceilf((h - 20.5f) * (1.0f / 14.0f)));
    int p1 = min(NP - 1, (int)floorf((h + 7.5f) * (1.0f / 14.0f)));
    int w0 = seg * 32;
    int qlo = max(0, (int)ceilf((w0 - 20.5f) * (1.0f / 14.0f)));
    int qhi = min(NP - 1, (int)floorf((w0 + 31 + 7.5f) * (1.0f / 14.0f)));

    unsigned int rem = 0xffffffffu;
    while (rem) {
        int leader = __ffs((int)rem) - 1;
        int lk = __shfl_sync(0xffffffffu, kk, leader);
        bool mine = (kk == lk);
        unsigned int mm = __ballot_sync(0xffffffffu, mine);
        for (int q = qlo; q <= qhi; q++) {
            float wtq = g_A[q * IMGSZ + w];          // exactly 0 outside support
            float v0 = mine ? wtq * r : 0.f;
            float v1 = mine ? wtq * g : 0.f;
            float v2 = mine ? wtq * bl : 0.f;
#pragma unroll
            for (int o = 16; o; o >>= 1) {
                v0 += __shfl_xor_sync(0xffffffffu, v0, o);
                v1 += __shfl_xor_sync(0xffffffffu, v1, o);
                v2 += __shfl_xor_sync(0xffffffffu, v2, o);
            }
            if (lane == leader) {
                for (int p = p0; p <= p1; p++) {
                    float wtp = g_A[p * IMGSZ + h];
                    if (wtp != 0.0f) {
                        float* dst = &g_acc[b][lk][p][q][0];
                        atomicAdd(dst + 0, wtp * v0);
                        atomicAdd(dst + 1, wtp * v1);
                        atomicAdd(dst + 2, wtp * v2);
                    }
                }
            }
        }
        rem &= ~mm;
    }
}

// ---------------- output permutation ----------------
__global__ void k_out(float* __restrict__ out) {
    int b = blockIdx.y;
    int lin = blockIdx.x * 1024 + threadIdx.x;       // < 76800
    float v = (&g_acc[b][0][0][0][0])[lin];
    int kc = lin >> 8;           // / 256
    int s  = lin & 255;          // % 256
    out[((size_t)b * 256 + s) * 300 + kc] = v;
}

// ---------------- launch ----------------
extern "C" void kernel_launch(void* const* d_in, const int* in_sizes, int n_in,
                              void* d_out, int out_size) {
    const float* x = (const float*)d_in[0];
    float* out = (float*)d_out;

    k_init<<<dim3(NB, 4), 256>>>(x);

    dim3 gt(NT, NB);                    // 196 x 8
    for (int it = 0; it < NITER; it++)
        k_assign_tile<<<gt, 256>>>(x, it, 1);
    k_assign_tile<<<gt, 256>>>(x, NITER, 0);   // final labels (centers from g_sum[9])

    k_scatter<<<dim3(NT, NB), 256>>>(x);       // 196 x 8 blocks, 8 warps each
    k_out<<<dim3(75, NB), 1024>>>(out);
}

// round 10
// speedup vs baseline: 2.3072x; 2.3072x over previous
#include <cuda_runtime.h>
#include <math.h>

#define IMGSZ 224
#define HW (IMGSZ*IMGSZ)     // 50176
#define NK 100
#define NP 16
#define NB 8
#define NT 196               // 14x14 tiles of 16x16 px
#define NITER 10

#define FIXSCALE 68719476736.0f   // 2^36
typedef unsigned long long u64;

// ---------------- device scratch (static, no runtime alloc) ----------------
__device__ float g_A[NP*IMGSZ];                   // resize matrix [16,224]
__device__ float g_centers[NB][NK][5];            // SLIC centers
__device__ unsigned char g_labels[NB][HW];        // per-pixel labels
__device__ u64 g_sum[NITER][NB][NK][6];           // per-iteration exact int64 sums
__device__ int g_ticket[NITER][NB];               // last-block tickets
__device__ float g_acc[NB][NK][NP][NP][3];        // output accumulator (2.4 MB)

__device__ __forceinline__ float slic_ratio() {
    return (float)(10.0 / sqrt(224.0 * 224.0 / 100.0));
}

// ---------------- init: A, centers, zero g_sum/g_acc/tickets ----------------
__global__ void k_init(const float* __restrict__ x) {
    int b = blockIdx.x;
    int part = blockIdx.y;           // 0..3
    int t = threadIdx.x;

    if (part == 0) {
        if (b == 0 && t < NP) {
            float sample = (t + 0.5f) * 14.0f - 0.5f;
            float total = 0.0f;
            for (int h = 0; h < IMGSZ; h++) {
                float d = fabsf(sample - (float)h) * (1.0f / 14.0f);
                float w = fmaxf(0.0f, 1.0f - d);
                g_A[t * IMGSZ + h] = w;
                total += w;
            }
            float inv = 1.0f / total;
            for (int h = 0; h < IMGSZ; h++) g_A[t * IMGSZ + h] *= inv;
        }
        if (t < NK) {
            const int cg[10] = {11, 33, 56, 78, 100, 123, 145, 168, 190, 212};
            int gy = t / 10, gx = t % 10;
            int h = cg[gy], w = cg[gx];
            const float* im = x + (size_t)b * 3 * HW;
            float ratio = slic_ratio();
            g_centers[b][t][0] = im[0 * HW + h * IMGSZ + w];
            g_centers[b][t][1] = im[1 * HW + h * IMGSZ + w];
            g_centers[b][t][2] = im[2 * HW + h * IMGSZ + w];
            g_centers[b][t][3] = (float)h * ratio;
            g_centers[b][t][4] = (float)w * ratio;
        }
        if (t < NITER) g_ticket[t][b] = 0;   // reset tickets EVERY launch (graph replays!)
    }
    // zero g_sum slice for image b (NITER*NK*6 = 6000 u64), split over 4 parts
    for (int j = part * 256 + t; j < NITER * NK * 6; j += 1024) {
        int it = j / (NK * 6), r = j % (NK * 6);
        g_sum[it][b][0][r] = 0ull;
    }
    // zero g_acc slice for image b (76800 floats), split over 4 parts
    {
        float4* ga = reinterpret_cast<float4*>(&g_acc[b][0][0][0][0]);
        for (int j = part * 256 + t; j < NK * NP * NP * 3 / 4; j += 1024)
            ga[j] = make_float4(0.f, 0.f, 0.f, 0.f);
    }
}

// ---------------- fused assign + int64 sums + last-block center update ------
// One block per 16x16 tile. Candidate pruning: center k excluded iff
// rectMinSpatial2(k) > min_j rectMaxSpatial2(j) + 3 (colors in [0,1) =>
// color dist^2 <= 3). Conservative => labels identical to full argmin.
// Accumulation: features scaled by 2^36 as u64, warp-segmented exact
// butterfly + one leader atomic per (warp,label). The LAST block per image
// (ticket) recomputes centers from the exact sums (double divide, once per
// image) and publishes g_centers for the next kernel launch.
__global__ __launch_bounds__(256) void k_assign_tile(const float* __restrict__ x,
                                                     int iter, int accumulate) {
    __shared__ float scen[NK][5];
    __shared__ float scen2[NK];
    __shared__ unsigned char scand[NK];
    __shared__ unsigned int bal[8];
    __shared__ int sminbits;
    __shared__ int is_last;

    int tile = blockIdx.x, b = blockIdx.y, t = threadIdx.x;
    int lane = t & 31, warp = t >> 5;
    const float ratio = slic_ratio();
    int tr = tile / 14, tc = tile - tr * 14;

    if (t == 0) sminbits = 0x7f7fffff;   // +FLT_MAX
    __syncthreads();

    // ---- candidate prologue ----
    float rmin = 1e30f, rmax = 1e30f;
    float c0 = 0.f, c1 = 0.f, c2 = 0.f, c3 = 0.f, c4 = 0.f;
    if (t < NK) {
        c0 = g_centers[b][t][0];
        c1 = g_centers[b][t][1];
        c2 = g_centers[b][t][2];
        c3 = g_centers[b][t][3];
        c4 = g_centers[b][t][4];
        float ylo = (float)(tr * 16) * ratio, yhi = (float)(tr * 16 + 15) * ratio;
        float xlo = (float)(tc * 16) * ratio, xhi = (float)(tc * 16 + 15) * ratio;
        float dy0 = fmaxf(0.0f, fmaxf(ylo - c3, c3 - yhi));
        float dx0 = fmaxf(0.0f, fmaxf(xlo - c4, c4 - xhi));
        float dy1 = fmaxf(c3 - ylo, yhi - c3);
        float dx1 = fmaxf(c4 - xlo, xhi - c4);
        rmin = dy0 * dy0 + dx0 * dx0;
        rmax = dy1 * dy1 + dx1 * dx1;
    }
    float v = rmax;
#pragma unroll
    for (int o = 16; o; o >>= 1) v = fminf(v, __shfl_xor_sync(0xffffffffu, v, o));
    if (lane == 0) atomicMin(&sminbits, __float_as_int(v));
    __syncthreads();
    float thresh = __int_as_float(sminbits) + 3.001f;
    bool keep = (t < NK) && (rmin <= thresh);
    unsigned int m = __ballot_sync(0xffffffffu, keep);
    if (lane == 0) bal[warp] = m;
    __syncthreads();
    if (keep) {
        int slot = __popc(m & ((1u << lane) - 1u));
        for (int w = 0; w < warp; w++) slot += __popc(bal[w]);
        scand[slot] = (unsigned char)t;
        scen[slot][0] = c0; scen[slot][1] = c1; scen[slot][2] = c2;
        scen[slot][3] = c3; scen[slot][4] = c4;
        scen2[slot] = c0*c0 + c1*c1 + c2*c2 + c3*c3 + c4*c4;
    }
    __syncthreads();
    int nc = 0;
#pragma unroll
    for (int w = 0; w < 8; w++) nc += __popc(bal[w]);

    // ---- per-pixel assignment ----
    int py = tr * 16 + (t >> 4), px = tc * 16 + (t & 15);
    int i = py * IMGSZ + px;
    const float* im = x + (size_t)b * 3 * HW;
    float f0 = im[i];
    float f1 = im[HW + i];
    float f2 = im[2 * HW + i];
    float f3 = (float)py * ratio;
    float f4 = (float)px * ratio;
    float fsq = f0*f0 + f1*f1 + f2*f2 + f3*f3 + f4*f4;

    float best = 3.4e38f;
    int bs = 0;
    for (int s = 0; s < nc; s++) {
        float dot = f0 * scen[s][0];
        dot = fmaf(f1, scen[s][1], dot);
        dot = fmaf(f2, scen[s][2], dot);
        dot = fmaf(f3, scen[s][3], dot);
        dot = fmaf(f4, scen[s][4], dot);
        float d = fsq + scen2[s] - 2.0f * dot;
        if (d < best) { best = d; bs = s; }   // strict < + ascending k => first-min
    }
    int kk = scand[bs];
    g_labels[b][i] = (unsigned char)kk;

    if (!accumulate) return;

    // ---- warp-segmented exact int64 accumulation ----
    u64 q0 = (u64)__float2ll_rn(f0 * FIXSCALE);
    u64 q1 = (u64)__float2ll_rn(f1 * FIXSCALE);
    u64 q2 = (u64)__float2ll_rn(f2 * FIXSCALE);
    u64 q3 = (u64)__float2ll_rn(f3 * FIXSCALE);
    u64 q4 = (u64)__float2ll_rn(f4 * FIXSCALE);

    unsigned int rem = 0xffffffffu;
    while (rem) {
        int leader = __ffs((int)rem) - 1;
        int lk = __shfl_sync(0xffffffffu, kk, leader);
        bool mine = (kk == lk);
        unsigned int mm = __ballot_sync(0xffffffffu, mine);
        u64 v0 = mine ? q0 : 0ull;
        u64 v1 = mine ? q1 : 0ull;
        u64 v2 = mine ? q2 : 0ull;
        u64 v3 = mine ? q3 : 0ull;
        u64 v4 = mine ? q4 : 0ull;
#pragma unroll
        for (int o = 16; o; o >>= 1) {
            v0 += __shfl_xor_sync(0xffffffffu, v0, o);
            v1 += __shfl_xor_sync(0xffffffffu, v1, o);
            v2 += __shfl_xor_sync(0xffffffffu, v2, o);
            v3 += __shfl_xor_sync(0xffffffffu, v3, o);
            v4 += __shfl_xor_sync(0xffffffffu, v4, o);
        }
        if (lane == leader) {
            u64* gs = &g_sum[iter][b][lk][0];
            atomicAdd(gs + 0, v0);
            atomicAdd(gs + 1, v1);
            atomicAdd(gs + 2, v2);
            atomicAdd(gs + 3, v3);
            atomicAdd(gs + 4, v4);
            atomicAdd(gs + 5, (u64)__popc(mm));
        }
        rem &= ~mm;
    }

    // ---- last block per image computes next centers (exact -> double) ----
    __threadfence();
    __syncthreads();
    if (t == 0) {
        int old = atomicAdd(&g_ticket[iter][b], 1);
        is_last = (old == NT - 1);
    }
    __syncthreads();
    if (is_last && t < NK) {
        const u64* gs = &g_sum[iter][b][t][0];
        u64 a0 = gs[0], a1 = gs[1], a2 = gs[2], a3 = gs[3], a4 = gs[4], a5 = gs[5];
        if (a5 > 0ull) {
            double inv = 1.0 / ((double)a5 * 68719476736.0);
            g_centers[b][t][0] = (float)((double)a0 * inv);
            g_centers[b][t][1] = (float)((double)a1 * inv);
            g_centers[b][t][2] = (float)((double)a2 * inv);
            g_centers[b][t][3] = (float)((double)a3 * inv);
            g_centers[b][t][4] = (float)((double)a4 * inv);
        }
        // a5 == 0: keep old center (matches jnp.where)
    }
}

// ---------------- scatter: pixel -> g_acc[b][k][p][q][c] (warp-aggregated) --
// warp = 32-pixel row segment; p-support & weights are warp-uniform (same h).
// For each distinct label in the warp and each q in the segment's support:
// 3-channel butterfly of wtq*rgb over member lanes, leader REDGs wtp*sum.
__global__ __launch_bounds__(256) void k_scatter(const float* __restrict__ x) {
    int b = blockIdx.y;
    int wi = blockIdx.x * 8 + (threadIdx.x >> 5);    // 0..1567
    int lane = threadIdx.x & 31;
    int h = wi / 7, seg = wi - (wi / 7) * 7;
    int w = seg * 32 + lane;
    int i = h * IMGSZ + w;
    const float* im = x + (size_t)b * 3 * HW;
    float r = im[i], g = im[HW + i], bl = im[2 * HW + i];
    int kk = g_labels[b][i];

    int p0 = max(0, (int)ceilf((h - 20.5f) * (1.0f / 14.0f)));
    int p1 = min(NP - 1, (int)floorf((h + 7.5f) * (1.0f / 14.0f)));
    int w0 = seg * 32;
    int qlo = max(0, (int)ceilf((w0 - 20.5f) * (1.0f / 14.0f)));
    int qhi = min(NP - 1, (int)floorf((w0 + 31 + 7.5f) * (1.0f / 14.0f)));

    unsigned int rem = 0xffffffffu;
    while (rem) {
        int leader = __ffs((int)rem) - 1;
        int lk = __shfl_sync(0xffffffffu, kk, leader);
        bool mine = (kk == lk);
        unsigned int mm = __ballot_sync(0xffffffffu, mine);
        for (int q = qlo; q <= qhi; q++) {
            float wtq = g_A[q * IMGSZ + w];          // exactly 0 outside support
            float v0 = mine ? wtq * r : 0.f;
            float v1 = mine ? wtq * g : 0.f;
            float v2 = mine ? wtq * bl : 0.f;
#pragma unroll
            for (int o = 16; o; o >>= 1) {
                v0 += __shfl_xor_sync(0xffffffffu, v0, o);
                v1 += __shfl_xor_sync(0xffffffffu, v1, o);
                v2 += __shfl_xor_sync(0xffffffffu, v2, o);
            }
            if (lane == leader) {
                for (int p = p0; p <= p1; p++) {
                    float wtp = g_A[p * IMGSZ + h];
                    if (wtp != 0.0f) {
                        float* dst = &g_acc[b][lk][p][q][0];
                        atomicAdd(dst + 0, wtp * v0);
                        atomicAdd(dst + 1, wtp * v1);
                        atomicAdd(dst + 2, wtp * v2);
                    }
                }
            }
        }
        rem &= ~mm;
    }
}

// ---------------- output permutation ----------------
__global__ void k_out(float* __restrict__ out) {
    int b = blockIdx.y;
    int lin = blockIdx.x * 1024 + threadIdx.x;       // < 76800
    float v = (&g_acc[b][0][0][0][0])[lin];
    int kc = lin >> 8;           // / 256
    int s  = lin & 255;          // % 256
    out[((size_t)b * 256 + s) * 300 + kc] = v;
}

// ---------------- launch ----------------
extern "C" void kernel_launch(void* const* d_in, const int* in_sizes, int n_in,
                              void* d_out, int out_size) {
    const float* x = (const float*)d_in[0];
    float* out = (float*)d_out;

    k_init<<<dim3(NB, 4), 256>>>(x);

    dim3 gt(NT, NB);                    // 196 x 8
    for (int it = 0; it < NITER; it++)
        k_assign_tile<<<gt, 256>>>(x, it, 1);
    k_assign_tile<<<gt, 256>>>(x, NITER, 0);   // final labels (centers from iter 9's last block)

    k_scatter<<<dim3(NT, NB), 256>>>(x);       // 196 x 8 blocks, 8 warps each
    k_out<<<dim3(75, NB), 1024>>>(out);
}

// round 11
// speedup vs baseline: 2.4753x; 1.0729x over previous
#include <cuda_runtime.h>
#include <math.h>

#define IMGSZ 224
#define HW (IMGSZ*IMGSZ)     // 50176
#define NK 100
#define NP 16
#define NB 8
#define NT 196               // 14x14 tiles of 16x16 px
#define NITER 10

#define FIXSCALE 68719476736.0f   // 2^36
typedef unsigned long long u64;
typedef unsigned int u32;

// ---------------- device scratch (static, no runtime alloc) ----------------
__device__ float g_A[NP*IMGSZ];                   // resize matrix [16,224]
__device__ float g_centers[NB][NK][5];            // SLIC centers
__device__ u64 g_sum[NITER][NB][NK][4];           // exact sums: 3 colors (2^36 fix) + packed(cnt,py,px)
__device__ int g_ticket[NITER][NB];               // last-block tickets
__device__ float g_acc[NB][NK][NP][NP][3];        // output accumulator (2.4 MB)

__device__ __forceinline__ float slic_ratio() {
    return (float)(10.0 / sqrt(224.0 * 224.0 / 100.0));
}

// ---------------- init: A, centers, zero g_sum/g_acc/tickets ----------------
__global__ void k_init(const float* __restrict__ x) {
    int b = blockIdx.x;
    int part = blockIdx.y;           // 0..3
    int t = threadIdx.x;

    if (part == 0) {
        if (b == 0 && t < NP) {
            float sample = (t + 0.5f) * 14.0f - 0.5f;
            float total = 0.0f;
            for (int h = 0; h < IMGSZ; h++) {
                float d = fabsf(sample - (float)h) * (1.0f / 14.0f);
                float w = fmaxf(0.0f, 1.0f - d);
                g_A[t * IMGSZ + h] = w;
                total += w;
            }
            float inv = 1.0f / total;
            for (int h = 0; h < IMGSZ; h++) g_A[t * IMGSZ + h] *= inv;
        }
        if (t < NK) {
            const int cg[10] = {11, 33, 56, 78, 100, 123, 145, 168, 190, 212};
            int gy = t / 10, gx = t % 10;
            int h = cg[gy], w = cg[gx];
            const float* im = x + (size_t)b * 3 * HW;
            float ratio = slic_ratio();
            g_centers[b][t][0] = im[0 * HW + h * IMGSZ + w];
            g_centers[b][t][1] = im[1 * HW + h * IMGSZ + w];
            g_centers[b][t][2] = im[2 * HW + h * IMGSZ + w];
            g_centers[b][t][3] = (float)h * ratio;
            g_centers[b][t][4] = (float)w * ratio;
        }
        if (t < NITER) g_ticket[t][b] = 0;   // reset EVERY launch (graph replays)
    }
    // zero g_sum slice for image b (NITER*NK*4 = 4000 u64), split over 4 parts
    for (int j = part * 256 + t; j < NITER * NK * 4; j += 1024)
        g_sum[j / (NK * 4)][b][0][j % (NK * 4)] = 0ull;
    // zero g_acc slice for image b (76800 floats = 19200 float4), split over 4 parts
    {
        float4* ga = reinterpret_cast<float4*>(&g_acc[b][0][0][0][0]);
        for (int j = part * 256 + t; j < NK * NP * NP * 3 / 4; j += 1024)
            ga[j] = make_float4(0.f, 0.f, 0.f, 0.f);
    }
}

// ---------------- fused assign + REDUX-aggregated exact sums + ticket -------
// One block per 16x16 tile. Candidate pruning: center k excluded iff
// rectMinSpatial2(k) > min_j rectMaxSpatial2(j) + 3 (colors in [0,1)).
// Conservative => labels identical to full argmin.
// Accumulation: colors quantized at 2^36, split 18/19 bits, warp-summed with
// __reduce_add_sync (exact; warp sums < 2^23). Spatial: exact integer
// sum(py), sum(px), cnt packed into one u64 (fields 16/24/24 bits, totals
// fit => no cross-field carry). Leader does 4 global atomics per
// (warp,label). LAST block per image (ticket) recomputes centers.
__global__ __launch_bounds__(256) void k_assign_tile(const float* __restrict__ x,
                                                     int iter) {
    __shared__ float scen[NK][5];
    __shared__ float scen2[NK];
    __shared__ unsigned char scand[NK];
    __shared__ unsigned int bal[8];
    __shared__ int sminbits;
    __shared__ int is_last;

    int tile = blockIdx.x, b = blockIdx.y, t = threadIdx.x;
    int lane = t & 31, warp = t >> 5;
    const float ratio = slic_ratio();
    int tr = tile / 14, tc = tile - tr * 14;

    if (t == 0) sminbits = 0x7f7fffff;   // +FLT_MAX
    __syncthreads();

    // ---- candidate prologue ----
    float rmin = 1e30f, rmax = 1e30f;
    float c0 = 0.f, c1 = 0.f, c2 = 0.f, c3 = 0.f, c4 = 0.f;
    if (t < NK) {
        c0 = g_centers[b][t][0];
        c1 = g_centers[b][t][1];
        c2 = g_centers[b][t][2];
        c3 = g_centers[b][t][3];
        c4 = g_centers[b][t][4];
        float ylo = (float)(tr * 16) * ratio, yhi = (float)(tr * 16 + 15) * ratio;
        float xlo = (float)(tc * 16) * ratio, xhi = (float)(tc * 16 + 15) * ratio;
        float dy0 = fmaxf(0.0f, fmaxf(ylo - c3, c3 - yhi));
        float dx0 = fmaxf(0.0f, fmaxf(xlo - c4, c4 - xhi));
        float dy1 = fmaxf(c3 - ylo, yhi - c3);
        float dx1 = fmaxf(c4 - xlo, xhi - c4);
        rmin = dy0 * dy0 + dx0 * dx0;
        rmax = dy1 * dy1 + dx1 * dx1;
    }
    u32 mn = __reduce_min_sync(0xffffffffu, __float_as_uint(rmax));  // nonneg floats
    if (lane == 0) atomicMin(&sminbits, (int)mn);
    __syncthreads();
    float thresh = __int_as_float(sminbits) + 3.001f;
    bool keep = (t < NK) && (rmin <= thresh);
    unsigned int m = __ballot_sync(0xffffffffu, keep);
    if (lane == 0) bal[warp] = m;
    __syncthreads();
    if (keep) {
        int slot = __popc(m & ((1u << lane) - 1u));
        for (int w2 = 0; w2 < warp; w2++) slot += __popc(bal[w2]);
        scand[slot] = (unsigned char)t;
        scen[slot][0] = c0; scen[slot][1] = c1; scen[slot][2] = c2;
        scen[slot][3] = c3; scen[slot][4] = c4;
        scen2[slot] = c0*c0 + c1*c1 + c2*c2 + c3*c3 + c4*c4;
    }
    __syncthreads();
    int nc = 0;
#pragma unroll
    for (int w2 = 0; w2 < 8; w2++) nc += __popc(bal[w2]);

    // ---- per-pixel assignment ----
    int py = tr * 16 + (t >> 4), px = tc * 16 + (t & 15);
    int i = py * IMGSZ + px;
    const float* im = x + (size_t)b * 3 * HW;
    float f0 = im[i];
    float f1 = im[HW + i];
    float f2 = im[2 * HW + i];
    float f3 = (float)py * ratio;
    float f4 = (float)px * ratio;
    float fsq = f0*f0 + f1*f1 + f2*f2 + f3*f3 + f4*f4;

    float best = 3.4e38f;
    int bs = 0;
    for (int s = 0; s < nc; s++) {
        float dot = f0 * scen[s][0];
        dot = fmaf(f1, scen[s][1], dot);
        dot = fmaf(f2, scen[s][2], dot);
        dot = fmaf(f3, scen[s][3], dot);
        dot = fmaf(f4, scen[s][4], dot);
        float d = fsq + scen2[s] - 2.0f * dot;
        if (d < best) { best = d; bs = s; }   // strict < + ascending k => first-min
    }
    int kk = scand[bs];

    // ---- REDUX-based exact accumulation ----
    u64 q0 = (u64)__float2ll_rn(f0 * FIXSCALE);   // < 2^36
    u64 q1 = (u64)__float2ll_rn(f1 * FIXSCALE);
    u64 q2 = (u64)__float2ll_rn(f2 * FIXSCALE);
    u32 l0 = (u32)q0 & 0x3FFFFu, h0 = (u32)(q0 >> 18);   // warp sums < 2^23
    u32 l1 = (u32)q1 & 0x3FFFFu, h1 = (u32)(q1 >> 18);
    u32 l2 = (u32)q2 & 0x3FFFFu, h2 = (u32)(q2 >> 18);

    unsigned int rem = 0xffffffffu;
    while (rem) {
        int leader = __ffs((int)rem) - 1;
        int lk = __shfl_sync(0xffffffffu, kk, leader);
        bool mine = (kk == lk);
        unsigned int mm = __ballot_sync(0xffffffffu, mine);
        if (mine) {
            u32 s0l = __reduce_add_sync(mm, l0);
            u32 s0h = __reduce_add_sync(mm, h0);
            u32 s1l = __reduce_add_sync(mm, l1);
            u32 s1h = __reduce_add_sync(mm, h1);
            u32 s2l = __reduce_add_sync(mm, l2);
            u32 s2h = __reduce_add_sync(mm, h2);
            u32 spy = __reduce_add_sync(mm, (u32)py);
            u32 spx = __reduce_add_sync(mm, (u32)px);
            if (lane == leader) {
                u64* gs = &g_sum[iter][b][lk][0];
                atomicAdd(gs + 0, ((u64)s0h << 18) + (u64)s0l);
                atomicAdd(gs + 1, ((u64)s1h << 18) + (u64)s1l);
                atomicAdd(gs + 2, ((u64)s2h << 18) + (u64)s2l);
                // packed: cnt [0:16) | sum_py [16:40) | sum_px [40:64)
                atomicAdd(gs + 3, (u64)__popc(mm) | ((u64)spy << 16) | ((u64)spx << 40));
            }
        }
        rem &= ~mm;
    }

    // ---- last block per image computes next centers ----
    __threadfence();
    __syncthreads();
    if (t == 0) {
        int old = atomicAdd(&g_ticket[iter][b], 1);
        is_last = (old == NT - 1);
    }
    __syncthreads();
    if (is_last && t < NK) {
        const u64* gs = &g_sum[iter][b][t][0];
        u64 a0 = gs[0], a1 = gs[1], a2 = gs[2], sp = gs[3];
        u64 cnt = sp & 0xFFFFull;
        u64 spy = (sp >> 16) & 0xFFFFFFull;
        u64 spx = sp >> 40;
        if (cnt > 0ull) {
            double invc = 1.0 / (double)cnt;
            double inv36 = invc * (1.0 / 68719476736.0);
            g_centers[b][t][0] = (float)((double)a0 * inv36);
            g_centers[b][t][1] = (float)((double)a1 * inv36);
            g_centers[b][t][2] = (float)((double)a2 * inv36);
            g_centers[b][t][3] = (float)((double)spy * invc * (double)ratio);
            g_centers[b][t][4] = (float)((double)spx * invc * (double)ratio);
        }
        // cnt == 0: keep old center (matches jnp.where)
    }
}

// ---------------- fused final-assign + scatter -------------------------------
// Block = 2 image rows (448 thr, 14 warps; warp = one 32-px row segment so
// h is warp-uniform). Prologue: candidate pruning over the 2-row strip,
// inline argmin (same math as k_assign_tile => labels identical). Then the
// R10 scatter: per distinct label, per q: 3-channel float butterfly of
// wtq*rgb over member lanes, leader REDGs wtp*sum into g_acc.
__global__ __launch_bounds__(448) void k_scatter(const float* __restrict__ x) {
    __shared__ float scen[NK][5];
    __shared__ float scen2[NK];
    __shared__ unsigned char scand[NK];
    __shared__ unsigned int bal[14];
    __shared__ int sminbits;

    int strip = blockIdx.x, b = blockIdx.y, t = threadIdx.x;
    int lane = t & 31, warp = t >> 5;
    const float ratio = slic_ratio();

    if (t == 0) sminbits = 0x7f7fffff;
    __syncthreads();

    float rmin = 1e30f, rmax = 1e30f;
    float c0 = 0.f, c1 = 0.f, c2 = 0.f, c3 = 0.f, c4 = 0.f;
    if (t < NK) {
        c0 = g_centers[b][t][0];
        c1 = g_centers[b][t][1];
        c2 = g_centers[b][t][2];
        c3 = g_centers[b][t][3];
        c4 = g_centers[b][t][4];
        float ylo = (float)(strip * 2) * ratio, yhi = (float)(strip * 2 + 1) * ratio;
        float xlo = 0.0f, xhi = 223.0f * ratio;
        float dy0 = fmaxf(0.0f, fmaxf(ylo - c3, c3 - yhi));
        float dx0 = fmaxf(0.0f, fmaxf(xlo - c4, c4 - xhi));
        float dy1 = fmaxf(c3 - ylo, yhi - c3);
        float dx1 = fmaxf(c4 - xlo, xhi - c4);
        rmin = dy0 * dy0 + dx0 * dx0;
        rmax = dy1 * dy1 + dx1 * dx1;
    }
    u32 mn = __reduce_min_sync(0xffffffffu, __float_as_uint(rmax));
    if (lane == 0) atomicMin(&sminbits, (int)mn);
    __syncthreads();
    float thresh = __int_as_float(sminbits) + 3.001f;
    bool keep = (t < NK) && (rmin <= thresh);
    unsigned int m = __ballot_sync(0xffffffffu, keep);
    if (lane == 0) bal[warp] = m;
    __syncthreads();
    if (keep) {
        int slot = __popc(m & ((1u << lane) - 1u));
        for (int w2 = 0; w2 < warp; w2++) slot += __popc(bal[w2]);
        scand[slot] = (unsigned char)t;
        scen[slot][0] = c0; scen[slot][1] = c1; scen[slot][2] = c2;
        scen[slot][3] = c3; scen[slot][4] = c4;
        scen2[slot] = c0*c0 + c1*c1 + c2*c2 + c3*c3 + c4*c4;
    }
    __syncthreads();
    int nc = 0;
#pragma unroll
    for (int w2 = 0; w2 < 14; w2++) nc += __popc(bal[w2]);

    // ---- pixel features + assignment ----
    int row = warp / 7, seg = warp - row * 7;
    int h = strip * 2 + row;
    int w = seg * 32 + lane;
    int i = h * IMGSZ + w;
    const float* im = x + (size_t)b * 3 * HW;
    float r = im[i], g = im[HW + i], bl = im[2 * HW + i];
    float f3 = (float)h * ratio;
    float f4 = (float)w * ratio;
    float fsq = r*r + g*g + bl*bl + f3*f3 + f4*f4;

    float best = 3.4e38f;
    int bs = 0;
    for (int s = 0; s < nc; s++) {
        float dot = r * scen[s][0];
        dot = fmaf(g,  scen[s][1], dot);
        dot = fmaf(bl, scen[s][2], dot);
        dot = fmaf(f3, scen[s][3], dot);
        dot = fmaf(f4, scen[s][4], dot);
        float d = fsq + scen2[s] - 2.0f * dot;
        if (d < best) { best = d; bs = s; }
    }
    int kk = scand[bs];

    // ---- scatter (h warp-uniform) ----
    int p0 = max(0, (int)ceilf((h - 20.5f) * (1.0f / 14.0f)));
    int p1 = min(NP - 1, (int)floorf((h + 7.5f) * (1.0f / 14.0f)));
    int w0 = seg * 32;
    int qlo = max(0, (int)ceilf((w0 - 20.5f) * (1.0f / 14.0f)));
    int qhi = min(NP - 1, (int)floorf((w0 + 31 + 7.5f) * (1.0f / 14.0f)));

    unsigned int rem = 0xffffffffu;
    while (rem) {
        int leader = __ffs((int)rem) - 1;
        int lk = __shfl_sync(0xffffffffu, kk, leader);
        bool mine = (kk == lk);
        unsigned int mm = __ballot_sync(0xffffffffu, mine);
        for (int q = qlo; q <= qhi; q++) {
            float wtq = g_A[q * IMGSZ + w];          // exactly 0 outside support
            float v0 = mine ? wtq * r  : 0.f;
            float v1 = mine ? wtq * g  : 0.f;
            float v2 = mine ? wtq * bl : 0.f;
#pragma unroll
            for (int o = 16; o; o >>= 1) {
                v0 += __shfl_xor_sync(0xffffffffu, v0, o);
                v1 += __shfl_xor_sync(0xffffffffu, v1, o);
                v2 += __shfl_xor_sync(0xffffffffu, v2, o);
            }
            if (lane == leader) {
                for (int p = p0; p <= p1; p++) {
                    float wtp = g_A[p * IMGSZ + h];
                    if (wtp != 0.0f) {
                        float* dst = &g_acc[b][lk][p][q][0];
                        atomicAdd(dst + 0, wtp * v0);
                        atomicAdd(dst + 1, wtp * v1);
                        atomicAdd(dst + 2, wtp * v2);
                    }
                }
            }
        }
        rem &= ~mm;
    }
}

// ---------------- output permutation ----------------
__global__ void k_out(float* __restrict__ out) {
    int b = blockIdx.y;
    int lin = blockIdx.x * 1024 + threadIdx.x;       // < 76800
    float v = (&g_acc[b][0][0][0][0])[lin];
    int kc = lin >> 8;           // / 256
    int s  = lin & 255;          // % 256
    out[((size_t)b * 256 + s) * 300 + kc] = v;
}

// ---------------- launch ----------------
extern "C" void kernel_launch(void* const* d_in, const int* in_sizes, int n_in,
                              void* d_out, int out_size) {
    const float* x = (const float*)d_in[0];
    float* out = (float*)d_out;

    k_init<<<dim3(NB, 4), 256>>>(x);

    dim3 gt(NT, NB);                    // 196 x 8
    for (int it = 0; it < NITER; it++)
        k_assign_tile<<<gt, 256>>>(x, it);

    k_scatter<<<dim3(112, NB), 448>>>(x);   // final assign fused with scatter
    k_out<<<dim3(75, NB), 1024>>>(out);
}